// round 14
// baseline (speedup 1.0000x reference)
#include <cuda_runtime.h>
#include <cstdint>

#define DROPOUT_R 0.2f
#define EPS_V 1e-8f

// One block per (b,c) row. Warp 0 computes the per-row scale
// (kept / (eps + proba_kept)); all threads then stream T floats as float4.
__global__ void __launch_bounds__(256, 8)
channel_dropout_kernel(const float* __restrict__ sig,
                       const float* __restrict__ pos,
                       const float* __restrict__ center,
                       const float* __restrict__ mc,
                       float* __restrict__ out,
                       int T, int nMC)
{
    const int row = blockIdx.x;
    __shared__ float s_scale;

    if (threadIdx.x < 32) {
        const float px = __ldg(&pos[2 * row + 0]);
        const float py = __ldg(&pos[2 * row + 1]);

        float cnt = 0.0f;
        for (int i = threadIdx.x; i < nMC; i += 32) {
            float dx = px - __ldg(&mc[2 * i + 0]);
            float dy = py - __ldg(&mc[2 * i + 1]);
            // match reference: norm > DROPOUT (sqrt then compare)
            cnt += (sqrtf(dx * dx + dy * dy) > DROPOUT_R) ? 1.0f : 0.0f;
        }
        #pragma unroll
        for (int o = 16; o > 0; o >>= 1)
            cnt += __shfl_xor_sync(0xFFFFFFFFu, cnt, o);

        if (threadIdx.x == 0) {
            float dx = px - __ldg(&center[0]);
            float dy = py - __ldg(&center[1]);
            float kept = (sqrtf(dx * dx + dy * dy) > DROPOUT_R) ? 1.0f : 0.0f;
            float proba = cnt / (float)nMC;
            s_scale = kept / (EPS_V + proba);
        }
    }
    __syncthreads();

    const float scale = s_scale;
    const size_t base = (size_t)row * (size_t)T;

    // vectorized main body (T=3000 is divisible by 4)
    const int n4 = T >> 2;
    const float4* __restrict__ in4  = reinterpret_cast<const float4*>(sig + base);
    float4* __restrict__       out4 = reinterpret_cast<float4*>(out + base);

    for (int i = threadIdx.x; i < n4; i += blockDim.x) {
        float4 v = in4[i];
        v.x *= scale; v.y *= scale; v.z *= scale; v.w *= scale;
        out4[i] = v;
    }
    // scalar tail (safety for T % 4 != 0)
    for (int i = (n4 << 2) + threadIdx.x; i < T; i += blockDim.x)
        out[base + i] = sig[base + i] * scale;
}

extern "C" void kernel_launch(void* const* d_in, const int* in_sizes, int n_in,
                              void* d_out, int out_size)
{
    const float* sig    = (const float*)d_in[0];   // (B, C, T)
    const float* pos    = (const float*)d_in[1];   // (B, C, 2)
    const float* center = (const float*)d_in[2];   // (2,)
    const float* mc     = (const float*)d_in[3];   // (N, 2)
    float* out = (float*)d_out;

    const int rows = in_sizes[1] / 2;              // B*C = 17472
    const int T    = in_sizes[0] / rows;           // 3000
    const int nMC  = in_sizes[3] / 2;              // 100

    channel_dropout_kernel<<<rows, 256>>>(sig, pos, center, mc, out, T, nMC);
}

// round 15
// speedup vs baseline: 1.0028x; 1.0028x over previous
#include <cuda_runtime.h>
#include <cstdint>

#define DROPOUT_R 0.2f
#define EPS_V 1e-8f
#define MAX_ROWS 32768
#define MAX_MC   512

// per-row scale scratch (no cudaMalloc allowed)
__device__ float g_scales[MAX_ROWS];

// ---------------------------------------------------------------------------
// Kernel 1: per-row scale = kept(center) / (eps + mean_i kept(mc_i))
// One thread per (b,c) row; mc staged in shared. ~2-3 us total.
// ---------------------------------------------------------------------------
__global__ void __launch_bounds__(256)
scales_kernel(const float* __restrict__ pos,
              const float* __restrict__ center,
              const float* __restrict__ mc,
              int rows, int nMC)
{
    __shared__ float2 s_mc[MAX_MC];
    __shared__ float2 s_ctr;

    for (int i = threadIdx.x; i < nMC; i += blockDim.x)
        s_mc[i] = reinterpret_cast<const float2*>(mc)[i];
    if (threadIdx.x == 0)
        s_ctr = reinterpret_cast<const float2*>(center)[0];
    __syncthreads();

    const int row = blockIdx.x * blockDim.x + threadIdx.x;
    if (row >= rows) return;

    const float2 p = reinterpret_cast<const float2*>(pos)[row];

    float cnt = 0.0f;
    #pragma unroll 4
    for (int i = 0; i < nMC; i++) {
        float dx = p.x - s_mc[i].x;
        float dy = p.y - s_mc[i].y;
        // match reference exactly: sqrt then compare
        cnt += (sqrtf(dx * dx + dy * dy) > DROPOUT_R) ? 1.0f : 0.0f;
    }

    float dx = p.x - s_ctr.x;
    float dy = p.y - s_ctr.y;
    float kept = (sqrtf(dx * dx + dy * dy) > DROPOUT_R) ? 1.0f : 0.0f;

    g_scales[row] = kept / (EPS_V + cnt / (float)nMC);
}

// ---------------------------------------------------------------------------
// Kernel 2: pure stream. One block per row, 512 threads, no barrier.
// T=3000 -> 750 float4 per row: thread t loads v[t] (always valid) and
// v[t+512] (if t<238), both issued back-to-back (MLP_p1=2), then stores.
// ---------------------------------------------------------------------------
__global__ void __launch_bounds__(512, 4)
scale_rows_kernel(const float* __restrict__ sig,
                  float* __restrict__ out,
                  int T)
{
    const int row = blockIdx.x;
    const float scale = g_scales[row];          // L1-resident after 1st wave
    const size_t base = (size_t)row * (size_t)T;

    const int n4 = T >> 2;
    const float4* __restrict__ in4  = reinterpret_cast<const float4*>(sig + base);
    float4* __restrict__       out4 = reinterpret_cast<float4*>(out + base);

    // batched grid-stride over the row: 2 independent loads per iteration
    for (int i = threadIdx.x; i < n4; i += (int)blockDim.x * 2) {
        const int j = i + (int)blockDim.x;
        float4 a = in4[i];
        float4 b;
        const bool hasb = j < n4;
        if (hasb) b = in4[j];

        a.x *= scale; a.y *= scale; a.z *= scale; a.w *= scale;
        out4[i] = a;
        if (hasb) {
            b.x *= scale; b.y *= scale; b.z *= scale; b.w *= scale;
            out4[j] = b;
        }
    }

    // scalar tail (T % 4 != 0 safety; no-op for T=3000)
    for (int i = (n4 << 2) + threadIdx.x; i < T; i += blockDim.x)
        out[base + i] = sig[base + i] * scale;
}

extern "C" void kernel_launch(void* const* d_in, const int* in_sizes, int n_in,
                              void* d_out, int out_size)
{
    const float* sig    = (const float*)d_in[0];   // (B, C, T)
    const float* pos    = (const float*)d_in[1];   // (B, C, 2)
    const float* center = (const float*)d_in[2];   // (2,)
    const float* mc     = (const float*)d_in[3];   // (N, 2)
    float* out = (float*)d_out;

    const int rows = in_sizes[1] / 2;              // B*C = 17472
    const int T    = in_sizes[0] / rows;           // 3000
    const int nMC  = in_sizes[3] / 2;              // 100

    scales_kernel<<<(rows + 255) / 256, 256>>>(pos, center, mc, rows, nMC);
    scale_rows_kernel<<<rows, 512>>>(sig, out, T);
}